// round 5
// baseline (speedup 1.0000x reference)
#include <cuda_runtime.h>
#include <cstdint>

// Problem constants
#define NIMG   32768
#define CC     14
#define CELLS  (32768 * 6 * 8)           // 1,572,864
#define TPB    256
#define CPT    256                       // cells per tile (1 per thread)
#define TILES  (CELLS / CPT)             // 6144, exact
#define V4PT   (CPT * CC / 4)            // 896 float4 per tensor per tile
#define GRIDN  296                       // 148 SMs x 2 resident blocks
#define NSTAGE 3
#define SMEM_BYTES (NSTAGE * 2 * V4PT * 16)  // 3 stages x 28KB = 86016

#define LAMBDA_COORD 8.0f
#define LAMBDA_NOOBJ 1.0f
#define LAMBDA_CLASS 0.7f
#define EPSV 1e-10f

__device__ float    g_partials[GRIDN];
__device__ unsigned g_count = 0;         // self-resetting block-arrival counter

__device__ __forceinline__ void cp16(float4* sdst, const float4* gsrc) {
    uint32_t s = (uint32_t)__cvta_generic_to_shared(sdst);
    asm volatile("cp.async.cg.shared.global [%0], [%1], 16;\n" :: "r"(s), "l"(gsrc));
}

// Stage one tile (both tensors) if it exists; ALWAYS commit a group so the
// wait_group counting stays invariant. 896 = 3*256 + 128.
__device__ __forceinline__ void stage_tile(float4* sbuf,
                                           const float4* __restrict__ out4,
                                           const float4* __restrict__ gt4,
                                           int tile, unsigned tid) {
    if (tile < TILES) {
        const size_t bv = (size_t)tile * V4PT;
#pragma unroll
        for (int i = 0; i < 3; ++i) {
            unsigned v = i * TPB + tid;
            cp16(sbuf + v, out4 + bv + v);
            cp16(sbuf + V4PT + v, gt4 + bv + v);
        }
        if (tid < V4PT - 3 * TPB) {
            unsigned v = 3 * TPB + tid;
            cp16(sbuf + v, out4 + bv + v);
            cp16(sbuf + V4PT + v, gt4 + bv + v);
        }
    }
    asm volatile("cp.async.commit_group;\n");
}

__device__ __forceinline__ float iou_f(float x1, float y1, float sw1, float sh1,
                                       float x2, float y2, float sw2, float sh2) {
    float w1 = sw1 * sw1, h1 = sh1 * sh1;
    float w2 = sw2 * sw2, h2 = sh2 * sh2;
    float left  = fmaxf(x1 - 0.5f * w1, x2 - 0.5f * w2);
    float right = fminf(x1 + 0.5f * w1, x2 + 0.5f * w2);
    float top   = fmaxf(y1 - 0.5f * h1, y2 - 0.5f * h2);
    float bot   = fminf(y1 + 0.5f * h1, y2 + 0.5f * h2);
    float inter = fmaxf(right - left, 0.0f) * fmaxf(bot - top, 0.0f);
    float uni   = w1 * h1 + w2 * h2 - inter;
    return inter / (uni + EPSV);
}

__device__ __forceinline__ float cell_loss(const float2* __restrict__ o2,
                                           const float2* __restrict__ g2) {
    float2 a0 = o2[0], a1 = o2[1], a2 = o2[2], a3 = o2[3], a4 = o2[4];
    float2 b0 = g2[0], b1 = g2[1], b2 = g2[2], b3 = g2[3], b4 = g2[4];

    float o0 = a0.x, o1 = a0.y, oc2 = a1.x, o3 = a1.y, o4 = a2.x;
    float o5 = a2.y, o6 = a3.x, o7 = a3.y, o8 = a4.x, o9 = a4.y;
    float g0 = b0.x, g1 = b0.y, gc2 = b1.x, g3 = b1.y, g4 = b2.x;
    float g5 = b2.y, g6 = b3.x, g7 = b3.y, g8 = b4.x, g9 = b4.y;

    float obj   = (g4 > 0.0f) ? 1.0f : 0.0f;
    float noobj = 1.0f - obj;

    float iou0 = iou_f(o0, o1, oc2, o3, g0, g1, gc2, g3);
    float iou1 = iou_f(o5, o6, o7, o8, g0, g1, gc2, g3);

    bool  sel1    = (iou1 > iou0);     // argmax tie-break: first index wins
    float max_iou = sel1 ? iou1 : iou0;

    float pr0 = sel1 ? o5 : o0;
    float pr1 = sel1 ? o6 : o1;
    float pr2 = sel1 ? o7 : oc2;
    float pr3 = sel1 ? o8 : o3;
    float pr4 = sel1 ? o9 : o4;
    float po4 = sel1 ? o4 : o9;

    float gr0 = sel1 ? g5 : g0;
    float gr1 = sel1 ? g6 : g1;
    float gr2 = sel1 ? g7 : gc2;
    float gr3 = sel1 ? g8 : g3;
    float go4 = sel1 ? g4 : g9;

    float d4 = o4 - g4, d9 = o9 - g9;
    float no_loss = noobj * (d4 * d4 + d9 * d9);

    float ec = pr4 - max_iou;
    float conf_loss = ec * ec;

    float l0 = pr0 - gr0, l1 = pr1 - gr1, l2 = pr2 - gr2, l3 = pr3 - gr3;
    float loc_loss = l0 * l0 + l1 * l1 + l2 * l2 + l3 * l3;

    float eo = po4 - go4;
    float nbc_loss = eo * eo;

    float2 a5 = o2[5], a6 = o2[6];
    float2 b5 = g2[5], b6 = g2[6];
    float c0 = a5.x - b5.x, c1 = a5.y - b5.y, c2v = a6.x - b6.x, c3 = a6.y - b6.y;
    float cls_loss = c0 * c0 + c1 * c1 + c2v * c2v + c3 * c3;

    return LAMBDA_NOOBJ * no_loss
         + obj * (conf_loss + LAMBDA_COORD * loc_loss
                  + LAMBDA_NOOBJ * nbc_loss + LAMBDA_CLASS * cls_loss);
}

__global__ void __launch_bounds__(TPB)
yolo_persistent_kernel(const float4* __restrict__ out4, const float4* __restrict__ gt4,
                       float* __restrict__ d_out) {
    extern __shared__ float4 smem[];     // [3][2*V4PT]: stage -> {o[896], g[896]}
    __shared__ float warpsum[TPB / 32];
    __shared__ bool  is_last;

    const unsigned tid  = threadIdx.x;
    const unsigned lane = tid & 31u;
    const unsigned wid  = tid >> 5;
    const unsigned bid  = blockIdx.x;

    float4* stage_base[NSTAGE];
    const float2* o2p[NSTAGE];
    const float2* g2p[NSTAGE];
#pragma unroll
    for (int s = 0; s < NSTAGE; ++s) {
        stage_base[s] = smem + s * (2 * V4PT);
        o2p[s] = (const float2*)((const char*)stage_base[s] + tid * 56u);
        g2p[s] = (const float2*)((const char*)(stage_base[s] + V4PT) + tid * 56u);
    }

    // Prologue: 2 tiles in flight.
    stage_tile(stage_base[0], out4, gt4, (int)bid,        tid);
    stage_tile(stage_base[1], out4, gt4, (int)bid + GRIDN, tid);

    float acc = 0.0f;
    unsigned s = 0;
    for (int cur = (int)bid; cur < TILES; cur += GRIDN) {
        // Oldest in-flight group (tile cur) must be complete.
        asm volatile("cp.async.wait_group 1;\n");
        // One barrier: data for `cur` visible to all warps AND all warps are
        // done reading the slot we are about to re-stage (tile cur-1's slot).
        __syncthreads();

        unsigned s2 = (s + 2 >= NSTAGE) ? s + 2 - NSTAGE : s + 2;
        stage_tile(stage_base[s2], out4, gt4, cur + 2 * GRIDN, tid);

        acc += cell_loss(o2p[s], g2p[s]);

        s = (s + 1 == NSTAGE) ? 0 : s + 1;
    }

    // Fixed-order block reduction
#pragma unroll
    for (int off = 16; off > 0; off >>= 1)
        acc += __shfl_down_sync(0xFFFFFFFFu, acc, off);
    if (lane == 0) warpsum[wid] = acc;
    __syncthreads();

    if (tid == 0) {
        float p = 0.0f;
#pragma unroll
        for (int w = 0; w < TPB / 32; ++w) p += warpsum[w];
        g_partials[bid] = p;
        __threadfence();
        unsigned old = atomicAdd(&g_count, 1u);
        is_last = (old == gridDim.x - 1);
    }
    __syncthreads();

    if (is_last) {
        double dacc = 0.0;
        for (int i = tid; i < GRIDN; i += TPB)
            dacc += (double)__ldcg(&g_partials[i]);
#pragma unroll
        for (int off = 16; off > 0; off >>= 1)
            dacc += __shfl_down_sync(0xFFFFFFFFu, dacc, off);

        __shared__ double dws[TPB / 32];
        if (lane == 0) dws[wid] = dacc;
        __syncthreads();
        if (tid == 0) {
            double total = 0.0;
#pragma unroll
            for (int w = 0; w < TPB / 32; ++w) total += dws[w];
            d_out[0] = (float)(total / (double)NIMG);
            g_count = 0;                  // reset for next graph replay
        }
    }
}

extern "C" void kernel_launch(void* const* d_in, const int* in_sizes, int n_in,
                              void* d_out, int out_size) {
    const float4* output = (const float4*)d_in[0];
    const float4* gtruth = (const float4*)d_in[1];
    float* outp = (float*)d_out;

    cudaFuncSetAttribute(yolo_persistent_kernel,
                         cudaFuncAttributeMaxDynamicSharedMemorySize, SMEM_BYTES);
    yolo_persistent_kernel<<<GRIDN, TPB, SMEM_BYTES>>>(output, gtruth, outp);
}

// round 6
// speedup vs baseline: 1.0508x; 1.0508x over previous
#include <cuda_runtime.h>
#include <cstdint>

// Problem constants
#define NIMG   32768
#define CC     14
#define CELLS  (32768 * 6 * 8)           // 1,572,864
#define TPB    512
#define CPT    512                       // cells per tile (1 per thread)
#define TILES  (CELLS / CPT)             // 3072, exact
#define V4PT   (CPT * CC / 4)            // 1792 float4 per tensor per tile
#define GRIDN  296                       // 148 SMs x 2 resident blocks
#define NSTAGE 2
#define SMEM_BYTES (NSTAGE * 2 * V4PT * 16)  // 2 stages x 56KB = 114688

#define LAMBDA_COORD 8.0f
#define LAMBDA_NOOBJ 1.0f
#define LAMBDA_CLASS 0.7f
#define EPSV 1e-10f

__device__ float    g_partials[GRIDN];
__device__ unsigned g_count = 0;         // self-resetting block-arrival counter

__device__ __forceinline__ void cp16(float4* sdst, const float4* gsrc) {
    uint32_t s = (uint32_t)__cvta_generic_to_shared(sdst);
    asm volatile("cp.async.cg.shared.global [%0], [%1], 16;\n" :: "r"(s), "l"(gsrc));
}

// Stage one tile (both tensors) if it exists; ALWAYS commit a group so the
// wait_group counting stays invariant. 1792 = 3*512 + 256.
__device__ __forceinline__ void stage_tile(float4* sbuf,
                                           const float4* __restrict__ out4,
                                           const float4* __restrict__ gt4,
                                           int tile, unsigned tid) {
    if (tile < TILES) {
        const size_t bv = (size_t)tile * V4PT;
#pragma unroll
        for (int i = 0; i < 3; ++i) {
            unsigned v = i * TPB + tid;
            cp16(sbuf + v, out4 + bv + v);
            cp16(sbuf + V4PT + v, gt4 + bv + v);
        }
        if (tid < V4PT - 3 * TPB) {
            unsigned v = 3 * TPB + tid;
            cp16(sbuf + v, out4 + bv + v);
            cp16(sbuf + V4PT + v, gt4 + bv + v);
        }
    }
    asm volatile("cp.async.commit_group;\n");
}

__device__ __forceinline__ float iou_f(float x1, float y1, float sw1, float sh1,
                                       float x2, float y2, float sw2, float sh2) {
    float w1 = sw1 * sw1, h1 = sh1 * sh1;
    float w2 = sw2 * sw2, h2 = sh2 * sh2;
    float left  = fmaxf(x1 - 0.5f * w1, x2 - 0.5f * w2);
    float right = fminf(x1 + 0.5f * w1, x2 + 0.5f * w2);
    float top   = fmaxf(y1 - 0.5f * h1, y2 - 0.5f * h2);
    float bot   = fminf(y1 + 0.5f * h1, y2 + 0.5f * h2);
    float inter = fmaxf(right - left, 0.0f) * fmaxf(bot - top, 0.0f);
    float uni   = w1 * h1 + w2 * h2 - inter;
    return inter / (uni + EPSV);
}

__device__ __forceinline__ float cell_loss(const float2* __restrict__ o2,
                                           const float2* __restrict__ g2) {
    float2 a0 = o2[0], a1 = o2[1], a2 = o2[2], a3 = o2[3], a4 = o2[4];
    float2 b0 = g2[0], b1 = g2[1], b2 = g2[2], b3 = g2[3], b4 = g2[4];

    float o0 = a0.x, o1 = a0.y, oc2 = a1.x, o3 = a1.y, o4 = a2.x;
    float o5 = a2.y, o6 = a3.x, o7 = a3.y, o8 = a4.x, o9 = a4.y;
    float g0 = b0.x, g1 = b0.y, gc2 = b1.x, g3 = b1.y, g4 = b2.x;
    float g5 = b2.y, g6 = b3.x, g7 = b3.y, g8 = b4.x, g9 = b4.y;

    float obj   = (g4 > 0.0f) ? 1.0f : 0.0f;
    float noobj = 1.0f - obj;

    float iou0 = iou_f(o0, o1, oc2, o3, g0, g1, gc2, g3);
    float iou1 = iou_f(o5, o6, o7, o8, g0, g1, gc2, g3);

    bool  sel1    = (iou1 > iou0);     // argmax tie-break: first index wins
    float max_iou = sel1 ? iou1 : iou0;

    float pr0 = sel1 ? o5 : o0;
    float pr1 = sel1 ? o6 : o1;
    float pr2 = sel1 ? o7 : oc2;
    float pr3 = sel1 ? o8 : o3;
    float pr4 = sel1 ? o9 : o4;
    float po4 = sel1 ? o4 : o9;

    float gr0 = sel1 ? g5 : g0;
    float gr1 = sel1 ? g6 : g1;
    float gr2 = sel1 ? g7 : gc2;
    float gr3 = sel1 ? g8 : g3;
    float go4 = sel1 ? g4 : g9;

    float d4 = o4 - g4, d9 = o9 - g9;
    float no_loss = noobj * (d4 * d4 + d9 * d9);

    float ec = pr4 - max_iou;
    float conf_loss = ec * ec;

    float l0 = pr0 - gr0, l1 = pr1 - gr1, l2 = pr2 - gr2, l3 = pr3 - gr3;
    float loc_loss = l0 * l0 + l1 * l1 + l2 * l2 + l3 * l3;

    float eo = po4 - go4;
    float nbc_loss = eo * eo;

    float2 a5 = o2[5], a6 = o2[6];
    float2 b5 = g2[5], b6 = g2[6];
    float c0 = a5.x - b5.x, c1 = a5.y - b5.y, c2v = a6.x - b6.x, c3 = a6.y - b6.y;
    float cls_loss = c0 * c0 + c1 * c1 + c2v * c2v + c3 * c3;

    return LAMBDA_NOOBJ * no_loss
         + obj * (conf_loss + LAMBDA_COORD * loc_loss
                  + LAMBDA_NOOBJ * nbc_loss + LAMBDA_CLASS * cls_loss);
}

__global__ void __launch_bounds__(TPB)
yolo_persistent_kernel(const float4* __restrict__ out4, const float4* __restrict__ gt4,
                       float* __restrict__ d_out) {
    extern __shared__ float4 smem[];     // [2][2*V4PT]: stage -> {o[1792], g[1792]}
    __shared__ float warpsum[TPB / 32];
    __shared__ bool  is_last;

    const unsigned tid  = threadIdx.x;
    const unsigned lane = tid & 31u;
    const unsigned wid  = tid >> 5;
    const unsigned bid  = blockIdx.x;

    float4* buf0 = smem;
    float4* buf1 = smem + 2 * V4PT;
    const float2* o2p0 = (const float2*)((const char*)buf0 + tid * 56u);
    const float2* g2p0 = (const float2*)((const char*)(buf0 + V4PT) + tid * 56u);
    const float2* o2p1 = (const float2*)((const char*)buf1 + tid * 56u);
    const float2* g2p1 = (const float2*)((const char*)(buf1 + V4PT) + tid * 56u);

    float acc = 0.0f;

    stage_tile(buf0, out4, gt4, (int)bid, tid);

    unsigned b = 0;
    for (int cur = (int)bid; cur < TILES; cur += GRIDN) {
        // Stage next tile into the other buffer, then wait for current.
        stage_tile(b ? buf0 : buf1, out4, gt4, cur + GRIDN, tid);
        asm volatile("cp.async.wait_group 1;\n");
        __syncthreads();

        acc += b ? cell_loss(o2p1, g2p1) : cell_loss(o2p0, g2p0);

        __syncthreads();                 // all reads done before re-staging this buffer
        b ^= 1u;
    }

    // Fixed-order block reduction
#pragma unroll
    for (int off = 16; off > 0; off >>= 1)
        acc += __shfl_down_sync(0xFFFFFFFFu, acc, off);
    if (lane == 0) warpsum[wid] = acc;
    __syncthreads();

    if (tid == 0) {
        float p = 0.0f;
#pragma unroll
        for (int w = 0; w < TPB / 32; ++w) p += warpsum[w];
        g_partials[bid] = p;
        __threadfence();
        unsigned old = atomicAdd(&g_count, 1u);
        is_last = (old == gridDim.x - 1);
    }
    __syncthreads();

    if (is_last) {
        double dacc = 0.0;
        for (int i = tid; i < GRIDN; i += TPB)
            dacc += (double)__ldcg(&g_partials[i]);
#pragma unroll
        for (int off = 16; off > 0; off >>= 1)
            dacc += __shfl_down_sync(0xFFFFFFFFu, dacc, off);

        __shared__ double dws[TPB / 32];
        if (lane == 0) dws[wid] = dacc;
        __syncthreads();
        if (tid == 0) {
            double total = 0.0;
#pragma unroll
            for (int w = 0; w < TPB / 32; ++w) total += dws[w];
            d_out[0] = (float)(total / (double)NIMG);
            g_count = 0;                  // reset for next graph replay
        }
    }
}

extern "C" void kernel_launch(void* const* d_in, const int* in_sizes, int n_in,
                              void* d_out, int out_size) {
    const float4* output = (const float4*)d_in[0];
    const float4* gtruth = (const float4*)d_in[1];
    float* outp = (float*)d_out;

    cudaFuncSetAttribute(yolo_persistent_kernel,
                         cudaFuncAttributeMaxDynamicSharedMemorySize, SMEM_BYTES);
    yolo_persistent_kernel<<<GRIDN, TPB, SMEM_BYTES>>>(output, gtruth, outp);
}

// round 7
// speedup vs baseline: 1.1089x; 1.0553x over previous
#include <cuda_runtime.h>
#include <cstdint>

// Problem constants
#define NIMG   32768
#define CC     14
#define CELLS  (32768 * 6 * 8)           // 1,572,864
#define TPB    256
#define CPT    256                       // cells per tile (1 per thread)
#define TILES  (CELLS / CPT)             // 6144, exact
#define V2PT   (CPT * CC / 2)            // 1792 float2 per tensor per tile
#define LPT    (V2PT / TPB)              // 7 float2 loads per thread per tensor

#define LAMBDA_COORD 8.0f
#define LAMBDA_NOOBJ 1.0f
#define LAMBDA_CLASS 0.7f
#define EPSV 1e-10f

__device__ float    g_partials[TILES];
__device__ unsigned g_count = 0;         // self-resetting block-arrival counter

__device__ __forceinline__ float iou_f(float x1, float y1, float sw1, float sh1,
                                       float x2, float y2, float sw2, float sh2) {
    float w1 = sw1 * sw1, h1 = sh1 * sh1;
    float w2 = sw2 * sw2, h2 = sh2 * sh2;
    float left  = fmaxf(x1 - 0.5f * w1, x2 - 0.5f * w2);
    float right = fminf(x1 + 0.5f * w1, x2 + 0.5f * w2);
    float top   = fmaxf(y1 - 0.5f * h1, y2 - 0.5f * h2);
    float bot   = fminf(y1 + 0.5f * h1, y2 + 0.5f * h2);
    float inter = fmaxf(right - left, 0.0f) * fmaxf(bot - top, 0.0f);
    float uni   = w1 * h1 + w2 * h2 - inter;
    return inter / (uni + EPSV);
}

__global__ void __launch_bounds__(TPB, 6)
yolo_kernel(const float2* __restrict__ out2, const float2* __restrict__ gt2,
            float* __restrict__ d_out) {
    __shared__ float2 s_o[V2PT];
    __shared__ float2 s_g[V2PT];
    __shared__ float  warpsum[TPB / 32];
    __shared__ bool   is_last;

    const unsigned tid  = threadIdx.x;
    const unsigned lane = tid & 31u;
    const unsigned wid  = tid >> 5;
    const unsigned tile = blockIdx.x;
    const size_t   bv   = (size_t)tile * V2PT;

    // 14 independent streaming LDG.64, front-batched for max MLP, then STS.64.
    float2 lo[LPT], lg[LPT];
#pragma unroll
    for (int i = 0; i < LPT; ++i) lo[i] = __ldcs(&out2[bv + i * TPB + tid]);
#pragma unroll
    for (int i = 0; i < LPT; ++i) lg[i] = __ldcs(&gt2[bv + i * TPB + tid]);
#pragma unroll
    for (int i = 0; i < LPT; ++i) s_o[i * TPB + tid] = lo[i];
#pragma unroll
    for (int i = 0; i < LPT; ++i) s_g[i * TPB + tid] = lg[i];
    __syncthreads();

    // One cell per thread: 14 floats at byte offset tid*56 -> 7 LDS.64 each.
    const float2* o2 = (const float2*)((const char*)s_o + tid * 56u);
    const float2* g2 = (const float2*)((const char*)s_g + tid * 56u);

    float2 a0 = o2[0], a1 = o2[1], a2 = o2[2], a3 = o2[3], a4 = o2[4];
    float2 b0 = g2[0], b1 = g2[1], b2 = g2[2], b3 = g2[3], b4 = g2[4];

    float o0 = a0.x, o1 = a0.y, oc2 = a1.x, o3 = a1.y, o4 = a2.x;
    float o5 = a2.y, o6 = a3.x, o7 = a3.y, o8 = a4.x, o9 = a4.y;
    float g0 = b0.x, g1 = b0.y, gc2 = b1.x, g3 = b1.y, g4 = b2.x;
    float g5 = b2.y, g6 = b3.x, g7 = b3.y, g8 = b4.x, g9 = b4.y;

    float obj   = (g4 > 0.0f) ? 1.0f : 0.0f;
    float noobj = 1.0f - obj;

    float iou0 = iou_f(o0, o1, oc2, o3, g0, g1, gc2, g3);
    float iou1 = iou_f(o5, o6, o7, o8, g0, g1, gc2, g3);

    bool  sel1    = (iou1 > iou0);     // argmax tie-break: first index wins
    float max_iou = sel1 ? iou1 : iou0;

    float pr0 = sel1 ? o5 : o0;
    float pr1 = sel1 ? o6 : o1;
    float pr2 = sel1 ? o7 : oc2;
    float pr3 = sel1 ? o8 : o3;
    float pr4 = sel1 ? o9 : o4;
    float po4 = sel1 ? o4 : o9;

    float gr0 = sel1 ? g5 : g0;
    float gr1 = sel1 ? g6 : g1;
    float gr2 = sel1 ? g7 : gc2;
    float gr3 = sel1 ? g8 : g3;
    float go4 = sel1 ? g4 : g9;

    float d4 = o4 - g4, d9 = o9 - g9;
    float no_loss = noobj * (d4 * d4 + d9 * d9);

    float ec = pr4 - max_iou;
    float conf_loss = ec * ec;

    float l0 = pr0 - gr0, l1 = pr1 - gr1, l2 = pr2 - gr2, l3 = pr3 - gr3;
    float loc_loss = l0 * l0 + l1 * l1 + l2 * l2 + l3 * l3;

    float eo = po4 - go4;
    float nbc_loss = eo * eo;

    float2 a5 = o2[5], a6 = o2[6];
    float2 b5 = g2[5], b6 = g2[6];
    float c0 = a5.x - b5.x, c1 = a5.y - b5.y, c2v = a6.x - b6.x, c3 = a6.y - b6.y;
    float cls_loss = c0 * c0 + c1 * c1 + c2v * c2v + c3 * c3;

    float cell = LAMBDA_NOOBJ * no_loss
               + obj * (conf_loss + LAMBDA_COORD * loc_loss
                        + LAMBDA_NOOBJ * nbc_loss + LAMBDA_CLASS * cls_loss);

    // Fixed-order block reduction
#pragma unroll
    for (int off = 16; off > 0; off >>= 1)
        cell += __shfl_down_sync(0xFFFFFFFFu, cell, off);
    if (lane == 0) warpsum[wid] = cell;
    __syncthreads();

    if (tid == 0) {
        float p = 0.0f;
#pragma unroll
        for (int w = 0; w < TPB / 32; ++w) p += warpsum[w];
        g_partials[tile] = p;
        __threadfence();
        unsigned old = atomicAdd(&g_count, 1u);
        is_last = (old == gridDim.x - 1);
    }
    __syncthreads();

    // Last-arriving block: deterministic final reduction of 6144 partials.
    if (is_last) {
        double dacc = 0.0;
#pragma unroll 8
        for (int i = tid; i < TILES; i += TPB)
            dacc += (double)__ldcg(&g_partials[i]);
#pragma unroll
        for (int off = 16; off > 0; off >>= 1)
            dacc += __shfl_down_sync(0xFFFFFFFFu, dacc, off);

        __shared__ double dws[TPB / 32];
        if (lane == 0) dws[wid] = dacc;
        __syncthreads();
        if (tid == 0) {
            double total = 0.0;
#pragma unroll
            for (int w = 0; w < TPB / 32; ++w) total += dws[w];
            d_out[0] = (float)(total / (double)NIMG);
            g_count = 0;                  // reset for next graph replay
        }
    }
}

extern "C" void kernel_launch(void* const* d_in, const int* in_sizes, int n_in,
                              void* d_out, int out_size) {
    const float2* output = (const float2*)d_in[0];
    const float2* gtruth = (const float2*)d_in[1];
    float* outp = (float*)d_out;

    yolo_kernel<<<TILES, TPB>>>(output, gtruth, outp);
}